// round 14
// baseline (speedup 1.0000x reference)
#include <cuda_runtime.h>
#include <cuda_fp16.h>

#define NB 8
#define NT 2048
#define NC 768
#define HS 64
#define BT (NB*NT)
// log2(e) / sqrt(768)
#define SL2E 0.0520587735f

typedef unsigned int uint32;

// ---------------- global scratch (allocation-free rule) ----------------
__device__ __align__(16) __half g_q[BT*HS];                 // fp16, pre-scaled
__device__ __align__(16) __half g_k[BT*HS];
__device__ __align__(16) __half g_v[BT*HS];
__device__ __align__(16) float g_opart[4][BT*HS];
__device__ float g_lpart[4][BT];
__device__ int g_cnt[NB*16];                                // split-arrival tickets
__device__ int g_next;                                      // attn work queue

// ---------------- helpers ----------------
__device__ __forceinline__ uint32 smem_u32(const void* p) {
    uint32 a;
    asm("{ .reg .u64 t; cvta.to.shared.u64 t, %1; cvt.u32.u64 %0, t; }" : "=r"(a) : "l"(p));
    return a;
}
__device__ __forceinline__ uint32 sw128(uint32 off) { return off ^ ((off >> 3) & 0x70); }

__device__ __forceinline__ void ldsm4(uint32 addr, uint32* r) {
    asm volatile("ldmatrix.sync.aligned.m8n8.x4.shared.b16 {%0,%1,%2,%3}, [%4];"
                 : "=r"(r[0]), "=r"(r[1]), "=r"(r[2]), "=r"(r[3]) : "r"(addr));
}
__device__ __forceinline__ void ldsm4t(uint32 addr, uint32* r) {
    asm volatile("ldmatrix.sync.aligned.m8n8.x4.trans.shared.b16 {%0,%1,%2,%3}, [%4];"
                 : "=r"(r[0]), "=r"(r[1]), "=r"(r[2]), "=r"(r[3]) : "r"(addr));
}
__device__ __forceinline__ void mma16816h(float* c, const uint32* a, uint32 b0, uint32 b1) {
    asm volatile("mma.sync.aligned.m16n8k16.row.col.f32.f16.f16.f32 "
                 "{%0,%1,%2,%3}, {%4,%5,%6,%7}, {%8,%9}, {%0,%1,%2,%3};"
                 : "+f"(c[0]), "+f"(c[1]), "+f"(c[2]), "+f"(c[3])
                 : "r"(a[0]), "r"(a[1]), "r"(a[2]), "r"(a[3]), "r"(b0), "r"(b1));
}
__device__ __forceinline__ uint32 packh2(float a, float b) {
    __half2 h = __floats2half2_rn(a, b);
    return *reinterpret_cast<uint32*>(&h);
}
__device__ __forceinline__ uint32 ex2h2(uint32 x) {
    uint32 y;
    asm("ex2.approx.f16x2 %0, %1;" : "=r"(y) : "r"(x));
    return y;
}
#define CP_ASYNC16(dst, src) \
    asm volatile("cp.async.cg.shared.global [%0], [%1], 16;" :: "r"(dst), "l"(src) : "memory")
#define CP_COMMIT asm volatile("cp.async.commit_group;" ::: "memory")
#define CP_WAIT0  asm volatile("cp.async.wait_group 0;" ::: "memory")

// ===========================================================================
// QKV (unchanged): 128x192 per CTA, K-chunk 64, fp16, 512 threads.
// ===========================================================================
#define XH 0
#define WH 16384
#define QSTG 41984
#define QKV_SMEM (2*QSTG)

__global__ __launch_bounds__(512, 1) void qkv_kernel(
    const float* __restrict__ x, const float* __restrict__ Wk,
    const float* __restrict__ Wq, const float* __restrict__ Wv)
{
    extern __shared__ char smem[];
    const int tid = threadIdx.x;
    const int wid = tid >> 5, lane = tid & 31;
    const int wm = wid & 3, wn = wid >> 2;
    const int row0 = blockIdx.x * 128;

    if (blockIdx.x == 0) {
        if (tid < NB * 16) g_cnt[tid] = 0;
        if (tid == 128) g_next = 0;
    }

    const uint32 sb = smem_u32(smem);

    float c[2][6][4];
    #pragma unroll
    for (int mi = 0; mi < 2; mi++)
        #pragma unroll
        for (int nj = 0; nj < 6; nj++)
            #pragma unroll
            for (int e = 0; e < 4; e++) c[mi][nj][e] = 0.f;

    float4 rx[2][2];
    float4 rw[6];

    {
        #pragma unroll
        for (int i = 0; i < 2; i++) {
            int f = tid + i * 512, r = f >> 3, g8 = (f & 7) * 8;
            const float* src = x + (size_t)(row0 + r) * NC + 0 + g8;
            rx[i][0] = *reinterpret_cast<const float4*>(src);
            rx[i][1] = *reinterpret_cast<const float4*>(src + 4);
        }
        #pragma unroll
        for (int i = 0; i < 6; i++) {
            int s_ = tid + i * 512;
            int kk = s_ / 48, q = s_ % 48;
            const float* W = (q < 16) ? Wq : ((q < 32) ? Wk : Wv);
            int nc = (q * 4) & 63;
            rw[i] = *reinterpret_cast<const float4*>(&W[(size_t)kk * HS + nc]);
        }
        #pragma unroll
        for (int i = 0; i < 2; i++) {
            int f = tid + i * 512, r = f >> 3, g8 = (f & 7) * 8;
            uint4 v = make_uint4(packh2(rx[i][0].x, rx[i][0].y), packh2(rx[i][0].z, rx[i][0].w),
                                 packh2(rx[i][1].x, rx[i][1].y), packh2(rx[i][1].z, rx[i][1].w));
            *reinterpret_cast<uint4*>(smem + XH + sw128((uint32)(r * 128 + g8 * 2))) = v;
        }
        #pragma unroll
        for (int i = 0; i < 6; i++) {
            int s_ = tid + i * 512;
            int kk = s_ / 48, q = s_ % 48;
            *reinterpret_cast<uint2*>(smem + WH + kk * 400 + q * 8)
                = make_uint2(packh2(rw[i].x, rw[i].y), packh2(rw[i].z, rw[i].w));
        }
    }

    for (int kc = 0; kc < 12; kc++) {
        const uint32 stb = sb + (kc & 1) * QSTG;
        char* nxt = smem + ((kc + 1) & 1) * QSTG;

        __syncthreads();

        if (kc < 11) {
            const int k0 = (kc + 1) * 64;
            #pragma unroll
            for (int i = 0; i < 2; i++) {
                int f = tid + i * 512, r = f >> 3, g8 = (f & 7) * 8;
                const float* src = x + (size_t)(row0 + r) * NC + k0 + g8;
                rx[i][0] = *reinterpret_cast<const float4*>(src);
                rx[i][1] = *reinterpret_cast<const float4*>(src + 4);
            }
            #pragma unroll
            for (int i = 0; i < 6; i++) {
                int s_ = tid + i * 512;
                int kk = s_ / 48, q = s_ % 48;
                const float* W = (q < 16) ? Wq : ((q < 32) ? Wk : Wv);
                int nc = (q * 4) & 63;
                rw[i] = *reinterpret_cast<const float4*>(&W[(size_t)(k0 + kk) * HS + nc]);
            }
        }

        #pragma unroll
        for (int ks = 0; ks < 4; ks++) {
            uint32 A[2][4];
            #pragma unroll
            for (int mi = 0; mi < 2; mi++) {
                uint32 off = sw128((uint32)((wm * 32 + mi * 16 + (lane & 15)) * 128
                                            + ks * 32 + (lane >> 4) * 16));
                ldsm4(stb + XH + off, A[mi]);
            }
            #pragma unroll
            for (int njp = 0; njp < 3; njp++) {
                int nabs = wn * 48 + njp * 16 + ((lane >> 4) & 1) * 8;
                int kl_ = ks * 16 + (lane & 15);
                uint32 boff = (uint32)(kl_ * 400 + nabs * 2);
                uint32 B[4];
                ldsm4t(stb + WH + boff, B);
                #pragma unroll
                for (int mi = 0; mi < 2; mi++)
                    #pragma unroll
                    for (int j = 0; j < 2; j++)
                        mma16816h(c[mi][njp * 2 + j], A[mi], B[2*j], B[2*j+1]);
            }
        }

        if (kc < 11) {
            #pragma unroll
            for (int i = 0; i < 2; i++) {
                int f = tid + i * 512, r = f >> 3, g8 = (f & 7) * 8;
                uint4 v = make_uint4(packh2(rx[i][0].x, rx[i][0].y), packh2(rx[i][0].z, rx[i][0].w),
                                     packh2(rx[i][1].x, rx[i][1].y), packh2(rx[i][1].z, rx[i][1].w));
                *reinterpret_cast<uint4*>(nxt + XH + sw128((uint32)(r * 128 + g8 * 2))) = v;
            }
            #pragma unroll
            for (int i = 0; i < 6; i++) {
                int s_ = tid + i * 512;
                int kk = s_ / 48, q = s_ % 48;
                *reinterpret_cast<uint2*>(nxt + WH + kk * 400 + q * 8)
                    = make_uint2(packh2(rw[i].x, rw[i].y), packh2(rw[i].z, rw[i].w));
            }
        }
    }

    const int g = lane >> 2, t = lane & 3;
    uint32* gq = reinterpret_cast<uint32*>(g_q);
    uint32* gk = reinterpret_cast<uint32*>(g_k);
    uint32* gv = reinterpret_cast<uint32*>(g_v);
    #pragma unroll
    for (int mi = 0; mi < 2; mi++)
        #pragma unroll
        for (int nj = 0; nj < 6; nj++)
            #pragma unroll
            for (int h = 0; h < 2; h++) {
                size_t row = (size_t)(row0 + wm * 32 + mi * 16 + h * 8 + g);
                int colp = wn * 24 + nj * 4 + t;
                float v0 = c[mi][nj][h * 2], v1 = c[mi][nj][h * 2 + 1];
                if (colp < 32)      gq[row * 32 + colp]      = packh2(v0 * SL2E, v1 * SL2E);
                else if (colp < 64) gk[row * 32 + colp - 32] = packh2(v0, v1);
                else                gv[row * 32 + colp - 64] = packh2(v0, v1);
            }
}

// ===========================================================================
// Attention (persistent, work-queue) + fused combine. grid 320, 3 CTAs/SM.
// Warp tile: 16 q-rows x ALL keys -> no cross-warp reduction at all.
// 64-key stages, computed in 32-key halves to cap registers.
// ===========================================================================
#define AQ_ 0
#define AST 16384
#define STG 16384
#define KH_ 0
#define VH_ 8192
#define AFL 49152
#define AUQ 49156
#define ATTN_SMEM 49184
#define NUNITS 320
#define ONESH2 0x3C003C00u

__device__ __forceinline__ void stage_kv_async(uint32 dstb, int b, int jt, int tid)
{
    const uint32* gk = reinterpret_cast<const uint32*>(g_k);
    const uint32* gv = reinterpret_cast<const uint32*>(g_v);
    size_t base = ((size_t)b * NT + (size_t)jt * 64) * 32;
    #pragma unroll
    for (int i = 0; i < 2; i++) {
        int f = tid + i * 256;
        int r = f >> 3, c16 = f & 7;
        uint32 off = sw128((uint32)(r * 128 + c16 * 16));
        size_t gidx = base + r * 32 + c16 * 4;
        CP_ASYNC16(dstb + KH_ + off, gk + gidx);
        CP_ASYNC16(dstb + VH_ + off, gv + gidx);
    }
}

__global__ __launch_bounds__(256, 3) void attn_kernel(float* __restrict__ out)
{
    extern __shared__ char smem[];
    const uint32 sb = smem_u32(smem);
    const int tid = threadIdx.x;
    const int wid = tid >> 5, lane = tid & 31;
    const int g = lane >> 2, t = lane & 3;

    volatile int* uqslot = reinterpret_cast<volatile int*>(smem + AUQ);
    volatile int* flag   = reinterpret_cast<volatile int*>(smem + AFL);

    for (;;) {
        __syncthreads();
        if (tid == 0) *uqslot = atomicAdd(&g_next, 1);
        __syncthreads();
        const int uq = *uqslot;
        if (uq >= NUNITS) break;

        const int b = uq & 7;
        const int u = 39 - (uq >> 3);
        int qi, s, ns;
        if (u < 4)       { qi = u;                  s = 0;            ns = 1; }
        else if (u < 12) { qi = 4 + ((u - 4) >> 1); s = (u - 4) & 1;  ns = 2; }
        else if (u < 24) { qi = 8 + (u - 12) / 3;   s = (u - 12) % 3; ns = 3; }
        else             { qi = 12 + ((u - 24) >> 2); s = (u - 24) & 3; ns = 4; }
        const int cnt = qi + 1;
        const int kb = 2 * (s * cnt / ns);
        const int ke = 2 * ((s + 1) * cnt / ns);

        // prologue: async stage Q tile + first K/V tile
        {
            const uint32* gq = reinterpret_cast<const uint32*>(g_q);
            size_t base = ((size_t)b * NT + (size_t)qi * 128) * 32;
            #pragma unroll
            for (int i = 0; i < 4; i++) {
                int f = tid + i * 256;
                int r = f >> 3, c16 = f & 7;
                uint32 off = sw128((uint32)(r * 128 + c16 * 16));
                CP_ASYNC16(sb + AQ_ + off, gq + base + r * 32 + c16 * 4);
            }
        }
        stage_kv_async(sb + AST, b, kb, tid);
        CP_COMMIT;

        float o[8][4];
        float lacc[4];
        #pragma unroll
        for (int e = 0; e < 4; e++) lacc[e] = 0.f;
        #pragma unroll
        for (int nj = 0; nj < 8; nj++)
            #pragma unroll
            for (int e = 0; e < 4; e++) o[nj][e] = 0.f;

        for (int jt = kb; jt < ke; jt++) {
            const int p = (jt - kb) & 1;
            const uint32 stb = sb + AST + p * STG;

            CP_WAIT0;
            __syncthreads();

            if (jt + 1 < ke) {
                stage_kv_async(sb + AST + (p ^ 1) * STG, b, jt + 1, tid);
                CP_COMMIT;
            }

            #pragma unroll
            for (int q2 = 0; q2 < 2; q2++) {   // 32-key halves
                // ---- S = Q K^T (16 rows x 32 keys) ----
                float sS[4][4];
                #pragma unroll
                for (int nj = 0; nj < 4; nj++)
                    #pragma unroll
                    for (int e = 0; e < 4; e++) sS[nj][e] = 0.f;

                #pragma unroll
                for (int ks = 0; ks < 4; ks++) {
                    uint32 A[4];
                    {
                        uint32 off = sw128((uint32)((wid * 16 + (lane & 15)) * 128
                                                    + ks * 32 + (lane >> 4) * 16));
                        ldsm4(sb + AQ_ + off, A);
                    }
                    #pragma unroll
                    for (int njp = 0; njp < 2; njp++) {
                        int row = q2 * 32 + njp * 16 + (lane & 7) + ((lane >> 4) & 1) * 8;
                        uint32 off = sw128((uint32)(row * 128 + ks * 32 + ((lane >> 3) & 1) * 16));
                        uint32 K[4];
                        ldsm4(stb + KH_ + off, K);
                        #pragma unroll
                        for (int j = 0; j < 2; j++)
                            mma16816h(sS[njp * 2 + j], A, K[2*j], K[2*j+1]);
                    }
                }

                // ---- mask (boundary tiles only) ----
                if (jt >= 2 * qi) {
                    const int kofs = jt * 64 - qi * 128 + q2 * 32;
                    #pragma unroll
                    for (int nj = 0; nj < 4; nj++)
                        #pragma unroll
                        for (int e = 0; e < 4; e++) {
                            int rl = wid * 16 + (e >> 1) * 8 + g;
                            int cl = nj * 8 + 2 * t + (e & 1);
                            if (cl + kofs > rl) sS[nj][e] = -1e30f;
                        }
                }

                // ---- P = exp2(S) f16x2, l += P x ones, O += P V ----
                #pragma unroll
                for (int kc = 0; kc < 2; kc++) {
                    uint32 aP[4];
                    aP[0] = ex2h2(packh2(sS[2*kc][0],   sS[2*kc][1]));
                    aP[1] = ex2h2(packh2(sS[2*kc][2],   sS[2*kc][3]));
                    aP[2] = ex2h2(packh2(sS[2*kc+1][0], sS[2*kc+1][1]));
                    aP[3] = ex2h2(packh2(sS[2*kc+1][2], sS[2*kc+1][3]));
                    mma16816h(lacc, aP, ONESH2, ONESH2);
                    #pragma unroll
                    for (int njp = 0; njp < 4; njp++) {
                        int kr = q2 * 32 + kc * 16 + (lane & 15);
                        int nn = njp * 16 + ((lane >> 4) & 1) * 8;
                        uint32 off = sw128((uint32)(kr * 128 + nn * 2));
                        uint32 V[4];
                        ldsm4t(stb + VH_ + off, V);
                        #pragma unroll
                        for (int j = 0; j < 2; j++)
                            mma16816h(o[njp * 2 + j], aP, V[2*j], V[2*j+1]);
                    }
                }
            }
        }

        // ---- direct output: warp owns rows [wid*16, wid*16+16) exclusively ----
        const size_t qbase = (size_t)b * NT + (size_t)qi * 128;
        const int ra = wid * 16 + g;           // row a; row b = ra + 8
        const float la = lacc[0], lb = lacc[2];

        if (ns == 1) {
            const float inva = 1.0f / la, invb = 1.0f / lb;
            #pragma unroll
            for (int nj = 0; nj < 8; nj++) {
                int col = nj * 8 + 2 * t;
                *reinterpret_cast<float2*>(&out[(qbase + ra) * 64 + col])
                    = make_float2(o[nj][0] * inva, o[nj][1] * inva);
                *reinterpret_cast<float2*>(&out[(qbase + ra + 8) * 64 + col])
                    = make_float2(o[nj][2] * invb, o[nj][3] * invb);
            }
        } else {
            float* op = g_opart[s];
            #pragma unroll
            for (int nj = 0; nj < 8; nj++) {
                int col = nj * 8 + 2 * t;
                *reinterpret_cast<float2*>(&op[(qbase + ra) * 64 + col])
                    = make_float2(o[nj][0], o[nj][1]);
                *reinterpret_cast<float2*>(&op[(qbase + ra + 8) * 64 + col])
                    = make_float2(o[nj][2], o[nj][3]);
            }
            if (t == 0) {
                g_lpart[s][qbase + ra] = la;
                g_lpart[s][qbase + ra + 8] = lb;
            }

            __threadfence();
            __syncthreads();
            if (tid == 0) {
                int ticket = atomicAdd(&g_cnt[b * 16 + qi], 1);
                *flag = (ticket == ns - 1) ? 1 : 0;
            }
            __syncthreads();
            if (*flag) {
                __threadfence();
                for (int idx = tid; idx < 2048; idx += 256) {
                    int r = idx >> 4, c4 = (idx & 15) << 2;
                    size_t rowg = qbase + r;
                    float l = 0.f;
                    float4 acc = make_float4(0.f, 0.f, 0.f, 0.f);
                    for (int s2 = 0; s2 < ns; s2++) {
                        float4 tv = *reinterpret_cast<const float4*>(&g_opart[s2][rowg * 64 + c4]);
                        acc.x += tv.x; acc.y += tv.y; acc.z += tv.z; acc.w += tv.w;
                        l += g_lpart[s2][rowg];
                    }
                    float inv = 1.0f / l;
                    acc.x *= inv; acc.y *= inv; acc.z *= inv; acc.w *= inv;
                    *reinterpret_cast<float4*>(&out[rowg * 64 + c4]) = acc;
                }
            }
        }
    }
}

// ===========================================================================
extern "C" void kernel_launch(void* const* d_in, const int* in_sizes, int n_in,
                              void* d_out, int out_size)
{
    const float* x  = (const float*)d_in[0];
    const float* Wk = (const float*)d_in[1];
    const float* Wq = (const float*)d_in[2];
    const float* Wv = (const float*)d_in[3];
    float* out = (float*)d_out;

    static bool attr_done = false;
    if (!attr_done) {
        cudaFuncSetAttribute(qkv_kernel,  cudaFuncAttributeMaxDynamicSharedMemorySize, QKV_SMEM);
        cudaFuncSetAttribute(attn_kernel, cudaFuncAttributeMaxDynamicSharedMemorySize, ATTN_SMEM);
        attr_done = true;
    }

    qkv_kernel<<<BT / 128, 512, QKV_SMEM>>>(x, Wk, Wq, Wv);
    attn_kernel<<<NUNITS, 256, ATTN_SMEM>>>(out);
}

// round 15
// speedup vs baseline: 1.0373x; 1.0373x over previous
#include <cuda_runtime.h>
#include <cuda_fp16.h>

#define NB 8
#define NT 2048
#define NC 768
#define HS 64
#define BT (NB*NT)
// log2(e) / sqrt(768)
#define SL2E 0.0520587735f

typedef unsigned int uint32;

// ---------------- global scratch (allocation-free rule) ----------------
__device__ __align__(16) __half g_q[BT*HS];                 // fp16, pre-scaled
__device__ __align__(16) __half g_k[BT*HS];
__device__ __align__(16) __half g_v[BT*HS];
__device__ __align__(16) float g_opart[4][BT*HS];
__device__ float g_lpart[4][BT];
__device__ int g_cnt[NB*16];                                // split-arrival tickets
__device__ int g_next;                                      // attn work queue

// ---------------- helpers ----------------
__device__ __forceinline__ uint32 smem_u32(const void* p) {
    uint32 a;
    asm("{ .reg .u64 t; cvta.to.shared.u64 t, %1; cvt.u32.u64 %0, t; }" : "=r"(a) : "l"(p));
    return a;
}
__device__ __forceinline__ uint32 sw128(uint32 off) { return off ^ ((off >> 3) & 0x70); }

__device__ __forceinline__ void ldsm4(uint32 addr, uint32* r) {
    asm volatile("ldmatrix.sync.aligned.m8n8.x4.shared.b16 {%0,%1,%2,%3}, [%4];"
                 : "=r"(r[0]), "=r"(r[1]), "=r"(r[2]), "=r"(r[3]) : "r"(addr));
}
__device__ __forceinline__ void ldsm4t(uint32 addr, uint32* r) {
    asm volatile("ldmatrix.sync.aligned.m8n8.x4.trans.shared.b16 {%0,%1,%2,%3}, [%4];"
                 : "=r"(r[0]), "=r"(r[1]), "=r"(r[2]), "=r"(r[3]) : "r"(addr));
}
// fp32-accumulate (qkv, PV, l)
__device__ __forceinline__ void mma16816h(float* c, const uint32* a, uint32 b0, uint32 b1) {
    asm volatile("mma.sync.aligned.m16n8k16.row.col.f32.f16.f16.f32 "
                 "{%0,%1,%2,%3}, {%4,%5,%6,%7}, {%8,%9}, {%0,%1,%2,%3};"
                 : "+f"(c[0]), "+f"(c[1]), "+f"(c[2]), "+f"(c[3])
                 : "r"(a[0]), "r"(a[1]), "r"(a[2]), "r"(a[3]), "r"(b0), "r"(b1));
}
// fp16-accumulate (S only)
__device__ __forceinline__ void mma16816hh(uint32* c, const uint32* a, uint32 b0, uint32 b1) {
    asm volatile("mma.sync.aligned.m16n8k16.row.col.f16.f16.f16.f16 "
                 "{%0,%1}, {%2,%3,%4,%5}, {%6,%7}, {%0,%1};"
                 : "+r"(c[0]), "+r"(c[1])
                 : "r"(a[0]), "r"(a[1]), "r"(a[2]), "r"(a[3]), "r"(b0), "r"(b1));
}
__device__ __forceinline__ uint32 packh2(float a, float b) {
    __half2 h = __floats2half2_rn(a, b);
    return *reinterpret_cast<uint32*>(&h);
}
__device__ __forceinline__ uint32 ex2h2(uint32 x) {
    uint32 y;
    asm("ex2.approx.f16x2 %0, %1;" : "=r"(y) : "r"(x));
    return y;
}
#define CP_ASYNC16(dst, src) \
    asm volatile("cp.async.cg.shared.global [%0], [%1], 16;" :: "r"(dst), "l"(src) : "memory")
#define CP_COMMIT asm volatile("cp.async.commit_group;" ::: "memory")
#define CP_WAIT0  asm volatile("cp.async.wait_group 0;" ::: "memory")

// ===========================================================================
// QKV (unchanged): 128x192 per CTA, K-chunk 64, fp16, 512 threads.
// ===========================================================================
#define XH 0
#define WH 16384
#define QSTG 41984
#define QKV_SMEM (2*QSTG)

__global__ __launch_bounds__(512, 1) void qkv_kernel(
    const float* __restrict__ x, const float* __restrict__ Wk,
    const float* __restrict__ Wq, const float* __restrict__ Wv)
{
    extern __shared__ char smem[];
    const int tid = threadIdx.x;
    const int wid = tid >> 5, lane = tid & 31;
    const int wm = wid & 3, wn = wid >> 2;
    const int row0 = blockIdx.x * 128;

    if (blockIdx.x == 0) {
        if (tid < NB * 16) g_cnt[tid] = 0;
        if (tid == 128) g_next = 0;
    }

    const uint32 sb = smem_u32(smem);

    float c[2][6][4];
    #pragma unroll
    for (int mi = 0; mi < 2; mi++)
        #pragma unroll
        for (int nj = 0; nj < 6; nj++)
            #pragma unroll
            for (int e = 0; e < 4; e++) c[mi][nj][e] = 0.f;

    float4 rx[2][2];
    float4 rw[6];

    {
        #pragma unroll
        for (int i = 0; i < 2; i++) {
            int f = tid + i * 512, r = f >> 3, g8 = (f & 7) * 8;
            const float* src = x + (size_t)(row0 + r) * NC + 0 + g8;
            rx[i][0] = *reinterpret_cast<const float4*>(src);
            rx[i][1] = *reinterpret_cast<const float4*>(src + 4);
        }
        #pragma unroll
        for (int i = 0; i < 6; i++) {
            int s_ = tid + i * 512;
            int kk = s_ / 48, q = s_ % 48;
            const float* W = (q < 16) ? Wq : ((q < 32) ? Wk : Wv);
            int nc = (q * 4) & 63;
            rw[i] = *reinterpret_cast<const float4*>(&W[(size_t)kk * HS + nc]);
        }
        #pragma unroll
        for (int i = 0; i < 2; i++) {
            int f = tid + i * 512, r = f >> 3, g8 = (f & 7) * 8;
            uint4 v = make_uint4(packh2(rx[i][0].x, rx[i][0].y), packh2(rx[i][0].z, rx[i][0].w),
                                 packh2(rx[i][1].x, rx[i][1].y), packh2(rx[i][1].z, rx[i][1].w));
            *reinterpret_cast<uint4*>(smem + XH + sw128((uint32)(r * 128 + g8 * 2))) = v;
        }
        #pragma unroll
        for (int i = 0; i < 6; i++) {
            int s_ = tid + i * 512;
            int kk = s_ / 48, q = s_ % 48;
            *reinterpret_cast<uint2*>(smem + WH + kk * 400 + q * 8)
                = make_uint2(packh2(rw[i].x, rw[i].y), packh2(rw[i].z, rw[i].w));
        }
    }

    for (int kc = 0; kc < 12; kc++) {
        const uint32 stb = sb + (kc & 1) * QSTG;
        char* nxt = smem + ((kc + 1) & 1) * QSTG;

        __syncthreads();

        if (kc < 11) {
            const int k0 = (kc + 1) * 64;
            #pragma unroll
            for (int i = 0; i < 2; i++) {
                int f = tid + i * 512, r = f >> 3, g8 = (f & 7) * 8;
                const float* src = x + (size_t)(row0 + r) * NC + k0 + g8;
                rx[i][0] = *reinterpret_cast<const float4*>(src);
                rx[i][1] = *reinterpret_cast<const float4*>(src + 4);
            }
            #pragma unroll
            for (int i = 0; i < 6; i++) {
                int s_ = tid + i * 512;
                int kk = s_ / 48, q = s_ % 48;
                const float* W = (q < 16) ? Wq : ((q < 32) ? Wk : Wv);
                int nc = (q * 4) & 63;
                rw[i] = *reinterpret_cast<const float4*>(&W[(size_t)(k0 + kk) * HS + nc]);
            }
        }

        #pragma unroll
        for (int ks = 0; ks < 4; ks++) {
            uint32 A[2][4];
            #pragma unroll
            for (int mi = 0; mi < 2; mi++) {
                uint32 off = sw128((uint32)((wm * 32 + mi * 16 + (lane & 15)) * 128
                                            + ks * 32 + (lane >> 4) * 16));
                ldsm4(stb + XH + off, A[mi]);
            }
            #pragma unroll
            for (int njp = 0; njp < 3; njp++) {
                int nabs = wn * 48 + njp * 16 + ((lane >> 4) & 1) * 8;
                int kl_ = ks * 16 + (lane & 15);
                uint32 boff = (uint32)(kl_ * 400 + nabs * 2);
                uint32 B[4];
                ldsm4t(stb + WH + boff, B);
                #pragma unroll
                for (int mi = 0; mi < 2; mi++)
                    #pragma unroll
                    for (int j = 0; j < 2; j++)
                        mma16816h(c[mi][njp * 2 + j], A[mi], B[2*j], B[2*j+1]);
            }
        }

        if (kc < 11) {
            #pragma unroll
            for (int i = 0; i < 2; i++) {
                int f = tid + i * 512, r = f >> 3, g8 = (f & 7) * 8;
                uint4 v = make_uint4(packh2(rx[i][0].x, rx[i][0].y), packh2(rx[i][0].z, rx[i][0].w),
                                     packh2(rx[i][1].x, rx[i][1].y), packh2(rx[i][1].z, rx[i][1].w));
                *reinterpret_cast<uint4*>(nxt + XH + sw128((uint32)(r * 128 + g8 * 2))) = v;
            }
            #pragma unroll
            for (int i = 0; i < 6; i++) {
                int s_ = tid + i * 512;
                int kk = s_ / 48, q = s_ % 48;
                *reinterpret_cast<uint2*>(nxt + WH + kk * 400 + q * 8)
                    = make_uint2(packh2(rw[i].x, rw[i].y), packh2(rw[i].z, rw[i].w));
            }
        }
    }

    const int g = lane >> 2, t = lane & 3;
    uint32* gq = reinterpret_cast<uint32*>(g_q);
    uint32* gk = reinterpret_cast<uint32*>(g_k);
    uint32* gv = reinterpret_cast<uint32*>(g_v);
    #pragma unroll
    for (int mi = 0; mi < 2; mi++)
        #pragma unroll
        for (int nj = 0; nj < 6; nj++)
            #pragma unroll
            for (int h = 0; h < 2; h++) {
                size_t row = (size_t)(row0 + wm * 32 + mi * 16 + h * 8 + g);
                int colp = wn * 24 + nj * 4 + t;
                float v0 = c[mi][nj][h * 2], v1 = c[mi][nj][h * 2 + 1];
                if (colp < 32)      gq[row * 32 + colp]      = packh2(v0 * SL2E, v1 * SL2E);
                else if (colp < 64) gk[row * 32 + colp - 32] = packh2(v0, v1);
                else                gv[row * 32 + colp - 64] = packh2(v0, v1);
            }
}

// ===========================================================================
// Attention (persistent, work-queue) + fused combine. grid 296, 2 CTAs/SM.
// R12 shape: 32q x 32k warps, 64-key stages. S in fp16 accumulators;
// S C-frag == PV A-frag, masked halves set to -inf (exp2 -> 0 exact).
// ===========================================================================
#define AQ_ 0
#define AST 16384
#define STG 16384
#define KH_ 0
#define VH_ 8192
#define AOB 0
#define ALB 49152
#define AFL (ALB + 1024)
#define AUQ (AFL + 4)
#define ATTN_SMEM (AUQ + 32)
#define NUNITS 320
#define ONESH2 0x3C003C00u
#define NINFH  0xFC00u

__device__ __forceinline__ void stage_kv_async(uint32 dstb, int b, int jt, int tid)
{
    const uint32* gk = reinterpret_cast<const uint32*>(g_k);
    const uint32* gv = reinterpret_cast<const uint32*>(g_v);
    size_t base = ((size_t)b * NT + (size_t)jt * 64) * 32;
    #pragma unroll
    for (int i = 0; i < 2; i++) {
        int f = tid + i * 256;
        int r = f >> 3, c16 = f & 7;
        uint32 off = sw128((uint32)(r * 128 + c16 * 16));
        size_t gidx = base + r * 32 + c16 * 4;
        CP_ASYNC16(dstb + KH_ + off, gk + gidx);
        CP_ASYNC16(dstb + VH_ + off, gv + gidx);
    }
}

__global__ __launch_bounds__(256, 2) void attn_kernel(float* __restrict__ out)
{
    extern __shared__ char smem[];
    const uint32 sb = smem_u32(smem);
    const int tid = threadIdx.x;
    const int wid = tid >> 5, lane = tid & 31;
    const int wm = wid & 3, wk = wid >> 2;
    const int g = lane >> 2, t = lane & 3;

    volatile int* uqslot = reinterpret_cast<volatile int*>(smem + AUQ);
    volatile int* flag   = reinterpret_cast<volatile int*>(smem + AFL);

    for (;;) {
        __syncthreads();
        if (tid == 0) *uqslot = atomicAdd(&g_next, 1);
        __syncthreads();
        const int uq = *uqslot;
        if (uq >= NUNITS) break;

        const int b = uq & 7;
        const int u = 39 - (uq >> 3);
        int qi, s, ns;
        if (u < 4)       { qi = u;                  s = 0;            ns = 1; }
        else if (u < 12) { qi = 4 + ((u - 4) >> 1); s = (u - 4) & 1;  ns = 2; }
        else if (u < 24) { qi = 8 + (u - 12) / 3;   s = (u - 12) % 3; ns = 3; }
        else             { qi = 12 + ((u - 24) >> 2); s = (u - 24) & 3; ns = 4; }
        const int cnt = qi + 1;
        const int kb = 2 * (s * cnt / ns);
        const int ke = 2 * ((s + 1) * cnt / ns);

        {
            const uint32* gq = reinterpret_cast<const uint32*>(g_q);
            size_t base = ((size_t)b * NT + (size_t)qi * 128) * 32;
            #pragma unroll
            for (int i = 0; i < 4; i++) {
                int f = tid + i * 256;
                int r = f >> 3, c16 = f & 7;
                uint32 off = sw128((uint32)(r * 128 + c16 * 16));
                CP_ASYNC16(sb + AQ_ + off, gq + base + r * 32 + c16 * 4);
            }
        }
        stage_kv_async(sb + AST, b, kb, tid);
        CP_COMMIT;

        float o[2][8][4];
        float lacc[2][4];
        #pragma unroll
        for (int mi = 0; mi < 2; mi++) {
            #pragma unroll
            for (int e = 0; e < 4; e++) lacc[mi][e] = 0.f;
            #pragma unroll
            for (int nj = 0; nj < 8; nj++)
                #pragma unroll
                for (int e = 0; e < 4; e++) o[mi][nj][e] = 0.f;
        }

        for (int jt = kb; jt < ke; jt++) {
            const int p = (jt - kb) & 1;
            const uint32 stb = sb + AST + p * STG;

            CP_WAIT0;
            __syncthreads();

            if (jt + 1 < ke) {
                stage_kv_async(sb + AST + (p ^ 1) * STG, b, jt + 1, tid);
                CP_COMMIT;
            }

            // ---- S = Q K^T in fp16 accumulators ----
            uint32 sS16[2][4][2];
            #pragma unroll
            for (int mi = 0; mi < 2; mi++)
                #pragma unroll
                for (int nj = 0; nj < 4; nj++) {
                    sS16[mi][nj][0] = 0u; sS16[mi][nj][1] = 0u;
                }

            #pragma unroll
            for (int ks = 0; ks < 4; ks++) {
                uint32 Q[2][4];
                #pragma unroll
                for (int mi = 0; mi < 2; mi++) {
                    uint32 off = sw128((uint32)((wm * 32 + mi * 16 + (lane & 15)) * 128
                                                + ks * 32 + (lane >> 4) * 16));
                    ldsm4(sb + AQ_ + off, Q[mi]);
                }
                #pragma unroll
                for (int njp = 0; njp < 2; njp++) {
                    int row = wk * 32 + njp * 16 + (lane & 7) + ((lane >> 4) & 1) * 8;
                    uint32 off = sw128((uint32)(row * 128 + ks * 32 + ((lane >> 3) & 1) * 16));
                    uint32 K[4];
                    ldsm4(stb + KH_ + off, K);
                    #pragma unroll
                    for (int mi = 0; mi < 2; mi++)
                        #pragma unroll
                        for (int j = 0; j < 2; j++)
                            mma16816hh(sS16[mi][njp * 2 + j], Q[mi], K[2*j], K[2*j+1]);
                }
            }

            // ---- mask (boundary tiles only): set halves to -inf ----
            if (jt >= 2 * qi) {
                const int kofs = jt * 64 - qi * 128;
                #pragma unroll
                for (int mi = 0; mi < 2; mi++)
                    #pragma unroll
                    for (int nj = 0; nj < 4; nj++)
                        #pragma unroll
                        for (int rr = 0; rr < 2; rr++) {
                            int rl = wm * 32 + mi * 16 + rr * 8 + g;
                            int cl = wk * 32 + nj * 8 + 2 * t;
                            uint32 v = sS16[mi][nj][rr];
                            if (cl + kofs > rl)     v = (v & 0xFFFF0000u) | NINFH;
                            if (cl + 1 + kofs > rl) v = (v & 0x0000FFFFu) | (NINFH << 16);
                            sS16[mi][nj][rr] = v;
                        }
            }

            // ---- P = exp2(S) f16x2 (C-frag == A-frag), l += P x 1, O += P V ----
            #pragma unroll
            for (int kc = 0; kc < 2; kc++) {
                uint32 aP[2][4];
                #pragma unroll
                for (int mi = 0; mi < 2; mi++) {
                    aP[mi][0] = ex2h2(sS16[mi][2*kc][0]);
                    aP[mi][1] = ex2h2(sS16[mi][2*kc][1]);
                    aP[mi][2] = ex2h2(sS16[mi][2*kc+1][0]);
                    aP[mi][3] = ex2h2(sS16[mi][2*kc+1][1]);
                    mma16816h(lacc[mi], aP[mi], ONESH2, ONESH2);
                }
                #pragma unroll
                for (int njp = 0; njp < 4; njp++) {
                    int kr = wk * 32 + kc * 16 + (lane & 15);
                    int nn = njp * 16 + ((lane >> 4) & 1) * 8;
                    uint32 off = sw128((uint32)(kr * 128 + nn * 2));
                    uint32 V[4];
                    ldsm4t(stb + VH_ + off, V);
                    #pragma unroll
                    for (int mi = 0; mi < 2; mi++)
                        #pragma unroll
                        for (int j = 0; j < 2; j++)
                            mma16816h(o[mi][njp * 2 + j], aP[mi], V[2*j], V[2*j+1]);
                }
            }
        }

        // ---- reductions & output (lacc cols are replicated row sums) ----
        __syncthreads();
        float* Obuf = reinterpret_cast<float*>(smem + AOB);
        float* lbuf = reinterpret_cast<float*>(smem + ALB);

        if (t == 0) {
            #pragma unroll
            for (int mi = 0; mi < 2; mi++) {
                lbuf[wk * 128 + wm * 32 + mi * 16 + g]     = lacc[mi][0];
                lbuf[wk * 128 + wm * 32 + mi * 16 + 8 + g] = lacc[mi][2];
            }
        }
        if (wk == 1) {
            #pragma unroll
            for (int mi = 0; mi < 2; mi++)
                #pragma unroll
                for (int nj = 0; nj < 8; nj++) {
                    int r0 = wm * 32 + mi * 16 + g;
                    int col = nj * 8 + 2 * t;
                    *reinterpret_cast<float2*>(&Obuf[r0 * 66 + col])
                        = make_float2(o[mi][nj][0], o[mi][nj][1]);
                    *reinterpret_cast<float2*>(&Obuf[(r0 + 8) * 66 + col])
                        = make_float2(o[mi][nj][2], o[mi][nj][3]);
                }
        }
        __syncthreads();

        const size_t qbase = (size_t)b * NT + (size_t)qi * 128;

        if (ns == 1) {
            if (wk == 0) {
                #pragma unroll
                for (int mi = 0; mi < 2; mi++) {
                    int ra = wm * 32 + mi * 16 + g;
                    float inva = 1.0f / (lbuf[ra] + lbuf[128 + ra]);
                    float invb = 1.0f / (lbuf[ra + 8] + lbuf[128 + ra + 8]);
                    #pragma unroll
                    for (int nj = 0; nj < 8; nj++) {
                        int col = nj * 8 + 2 * t;
                        float2 u0 = *reinterpret_cast<float2*>(&Obuf[ra * 66 + col]);
                        float2 u1 = *reinterpret_cast<float2*>(&Obuf[(ra + 8) * 66 + col]);
                        *reinterpret_cast<float2*>(&out[(qbase + ra) * 64 + col])
                            = make_float2((o[mi][nj][0] + u0.x) * inva, (o[mi][nj][1] + u0.y) * inva);
                        *reinterpret_cast<float2*>(&out[(qbase + ra + 8) * 64 + col])
                            = make_float2((o[mi][nj][2] + u1.x) * invb, (o[mi][nj][3] + u1.y) * invb);
                    }
                }
            }
        } else {
            if (wk == 0) {
                float* op = g_opart[s];
                #pragma unroll
                for (int mi = 0; mi < 2; mi++)
                    #pragma unroll
                    for (int nj = 0; nj < 8; nj++) {
                        int r0 = wm * 32 + mi * 16 + g;
                        int col = nj * 8 + 2 * t;
                        float2 u0 = *reinterpret_cast<float2*>(&Obuf[r0 * 66 + col]);
                        float2 u1 = *reinterpret_cast<float2*>(&Obuf[(r0 + 8) * 66 + col]);
                        *reinterpret_cast<float2*>(&op[(qbase + r0) * 64 + col])
                            = make_float2(o[mi][nj][0] + u0.x, o[mi][nj][1] + u0.y);
                        *reinterpret_cast<float2*>(&op[(qbase + r0 + 8) * 64 + col])
                            = make_float2(o[mi][nj][2] + u1.x, o[mi][nj][3] + u1.y);
                    }
            }
            if (tid < 128)
                g_lpart[s][qbase + tid] = lbuf[tid] + lbuf[128 + tid];

            __threadfence();
            __syncthreads();
            if (tid == 0) {
                int ticket = atomicAdd(&g_cnt[b * 16 + qi], 1);
                *flag = (ticket == ns - 1) ? 1 : 0;
            }
            __syncthreads();
            if (*flag) {
                __threadfence();
                for (int idx = tid; idx < 2048; idx += 256) {
                    int r = idx >> 4, c4 = (idx & 15) << 2;
                    size_t rowg = qbase + r;
                    float l = 0.f;
                    float4 acc = make_float4(0.f, 0.f, 0.f, 0.f);
                    for (int s2 = 0; s2 < ns; s2++) {
                        float4 tv = *reinterpret_cast<const float4*>(&g_opart[s2][rowg * 64 + c4]);
                        acc.x += tv.x; acc.y += tv.y; acc.z += tv.z; acc.w += tv.w;
                        l += g_lpart[s2][rowg];
                    }
                    float inv = 1.0f / l;
                    acc.x *= inv; acc.y *= inv; acc.z *= inv; acc.w *= inv;
                    *reinterpret_cast<float4*>(&out[rowg * 64 + c4]) = acc;
                }
            }
        }
    }
}

// ===========================================================================
extern "C" void kernel_launch(void* const* d_in, const int* in_sizes, int n_in,
                              void* d_out, int out_size)
{
    const float* x  = (const float*)d_in[0];
    const float* Wk = (const float*)d_in[1];
    const float* Wq = (const float*)d_in[2];
    const float* Wv = (const float*)d_in[3];
    float* out = (float*)d_out;

    static bool attr_done = false;
    if (!attr_done) {
        cudaFuncSetAttribute(qkv_kernel,  cudaFuncAttributeMaxDynamicSharedMemorySize, QKV_SMEM);
        cudaFuncSetAttribute(attn_kernel, cudaFuncAttributeMaxDynamicSharedMemorySize, ATTN_SMEM);
        attr_done = true;
    }

    qkv_kernel<<<BT / 128, 512, QKV_SMEM>>>(x, Wk, Wq, Wv);
    attn_kernel<<<296, 256, ATTN_SMEM>>>(out);
}

// round 16
// speedup vs baseline: 1.0717x; 1.0332x over previous
#include <cuda_runtime.h>
#include <cuda_fp16.h>

#define NB 8
#define NT 2048
#define NC 768
#define HS 64
#define BT (NB*NT)
// log2(e) / sqrt(768)
#define SL2E 0.0520587735f

typedef unsigned int uint32;

// ---------------- global scratch (allocation-free rule) ----------------
__device__ __align__(16) __half g_q[BT*HS];                 // fp16, pre-scaled
__device__ __align__(16) __half g_k[BT*HS];
__device__ __align__(16) __half g_v[BT*HS];
__device__ __align__(16) float g_opart[4][BT*HS];
__device__ float g_lpart[4][BT];
__device__ int g_cnt[NB*16];                                // split-arrival tickets
__device__ int g_next;                                      // attn work queue

// ---------------- helpers ----------------
__device__ __forceinline__ uint32 smem_u32(const void* p) {
    uint32 a;
    asm("{ .reg .u64 t; cvta.to.shared.u64 t, %1; cvt.u32.u64 %0, t; }" : "=r"(a) : "l"(p));
    return a;
}
__device__ __forceinline__ uint32 sw128(uint32 off) { return off ^ ((off >> 3) & 0x70); }

__device__ __forceinline__ void ldsm4(uint32 addr, uint32* r) {
    asm volatile("ldmatrix.sync.aligned.m8n8.x4.shared.b16 {%0,%1,%2,%3}, [%4];"
                 : "=r"(r[0]), "=r"(r[1]), "=r"(r[2]), "=r"(r[3]) : "r"(addr));
}
__device__ __forceinline__ void ldsm4t(uint32 addr, uint32* r) {
    asm volatile("ldmatrix.sync.aligned.m8n8.x4.trans.shared.b16 {%0,%1,%2,%3}, [%4];"
                 : "=r"(r[0]), "=r"(r[1]), "=r"(r[2]), "=r"(r[3]) : "r"(addr));
}
// fp32-accumulate (qkv, PV, l)
__device__ __forceinline__ void mma16816h(float* c, const uint32* a, uint32 b0, uint32 b1) {
    asm volatile("mma.sync.aligned.m16n8k16.row.col.f32.f16.f16.f32 "
                 "{%0,%1,%2,%3}, {%4,%5,%6,%7}, {%8,%9}, {%0,%1,%2,%3};"
                 : "+f"(c[0]), "+f"(c[1]), "+f"(c[2]), "+f"(c[3])
                 : "r"(a[0]), "r"(a[1]), "r"(a[2]), "r"(a[3]), "r"(b0), "r"(b1));
}
// fp16-accumulate (S only)
__device__ __forceinline__ void mma16816hh(uint32* c, const uint32* a, uint32 b0, uint32 b1) {
    asm volatile("mma.sync.aligned.m16n8k16.row.col.f16.f16.f16.f16 "
                 "{%0,%1}, {%2,%3,%4,%5}, {%6,%7}, {%0,%1};"
                 : "+r"(c[0]), "+r"(c[1])
                 : "r"(a[0]), "r"(a[1]), "r"(a[2]), "r"(a[3]), "r"(b0), "r"(b1));
}
__device__ __forceinline__ uint32 packh2(float a, float b) {
    __half2 h = __floats2half2_rn(a, b);
    return *reinterpret_cast<uint32*>(&h);
}
__device__ __forceinline__ uint32 ex2h2(uint32 x) {
    uint32 y;
    asm("ex2.approx.f16x2 %0, %1;" : "=r"(y) : "r"(x));
    return y;
}
#define CP_ASYNC16(dst, src) \
    asm volatile("cp.async.cg.shared.global [%0], [%1], 16;" :: "r"(dst), "l"(src) : "memory")
#define CP_COMMIT asm volatile("cp.async.commit_group;" ::: "memory")
#define CP_WAIT0  asm volatile("cp.async.wait_group 0;" ::: "memory")

// ===========================================================================
// QKV (unchanged): 128x192 per CTA, K-chunk 64, fp16, 512 threads.
// ===========================================================================
#define XH 0
#define WH 16384
#define QSTG 41984
#define QKV_SMEM (2*QSTG)

__global__ __launch_bounds__(512, 1) void qkv_kernel(
    const float* __restrict__ x, const float* __restrict__ Wk,
    const float* __restrict__ Wq, const float* __restrict__ Wv)
{
    extern __shared__ char smem[];
    const int tid = threadIdx.x;
    const int wid = tid >> 5, lane = tid & 31;
    const int wm = wid & 3, wn = wid >> 2;
    const int row0 = blockIdx.x * 128;

    if (blockIdx.x == 0) {
        if (tid < NB * 16) g_cnt[tid] = 0;
        if (tid == 128) g_next = 0;
    }

    const uint32 sb = smem_u32(smem);

    float c[2][6][4];
    #pragma unroll
    for (int mi = 0; mi < 2; mi++)
        #pragma unroll
        for (int nj = 0; nj < 6; nj++)
            #pragma unroll
            for (int e = 0; e < 4; e++) c[mi][nj][e] = 0.f;

    float4 rx[2][2];
    float4 rw[6];

    {
        #pragma unroll
        for (int i = 0; i < 2; i++) {
            int f = tid + i * 512, r = f >> 3, g8 = (f & 7) * 8;
            const float* src = x + (size_t)(row0 + r) * NC + 0 + g8;
            rx[i][0] = *reinterpret_cast<const float4*>(src);
            rx[i][1] = *reinterpret_cast<const float4*>(src + 4);
        }
        #pragma unroll
        for (int i = 0; i < 6; i++) {
            int s_ = tid + i * 512;
            int kk = s_ / 48, q = s_ % 48;
            const float* W = (q < 16) ? Wq : ((q < 32) ? Wk : Wv);
            int nc = (q * 4) & 63;
            rw[i] = *reinterpret_cast<const float4*>(&W[(size_t)kk * HS + nc]);
        }
        #pragma unroll
        for (int i = 0; i < 2; i++) {
            int f = tid + i * 512, r = f >> 3, g8 = (f & 7) * 8;
            uint4 v = make_uint4(packh2(rx[i][0].x, rx[i][0].y), packh2(rx[i][0].z, rx[i][0].w),
                                 packh2(rx[i][1].x, rx[i][1].y), packh2(rx[i][1].z, rx[i][1].w));
            *reinterpret_cast<uint4*>(smem + XH + sw128((uint32)(r * 128 + g8 * 2))) = v;
        }
        #pragma unroll
        for (int i = 0; i < 6; i++) {
            int s_ = tid + i * 512;
            int kk = s_ / 48, q = s_ % 48;
            *reinterpret_cast<uint2*>(smem + WH + kk * 400 + q * 8)
                = make_uint2(packh2(rw[i].x, rw[i].y), packh2(rw[i].z, rw[i].w));
        }
    }

    for (int kc = 0; kc < 12; kc++) {
        const uint32 stb = sb + (kc & 1) * QSTG;
        char* nxt = smem + ((kc + 1) & 1) * QSTG;

        __syncthreads();

        if (kc < 11) {
            const int k0 = (kc + 1) * 64;
            #pragma unroll
            for (int i = 0; i < 2; i++) {
                int f = tid + i * 512, r = f >> 3, g8 = (f & 7) * 8;
                const float* src = x + (size_t)(row0 + r) * NC + k0 + g8;
                rx[i][0] = *reinterpret_cast<const float4*>(src);
                rx[i][1] = *reinterpret_cast<const float4*>(src + 4);
            }
            #pragma unroll
            for (int i = 0; i < 6; i++) {
                int s_ = tid + i * 512;
                int kk = s_ / 48, q = s_ % 48;
                const float* W = (q < 16) ? Wq : ((q < 32) ? Wk : Wv);
                int nc = (q * 4) & 63;
                rw[i] = *reinterpret_cast<const float4*>(&W[(size_t)(k0 + kk) * HS + nc]);
            }
        }

        #pragma unroll
        for (int ks = 0; ks < 4; ks++) {
            uint32 A[2][4];
            #pragma unroll
            for (int mi = 0; mi < 2; mi++) {
                uint32 off = sw128((uint32)((wm * 32 + mi * 16 + (lane & 15)) * 128
                                            + ks * 32 + (lane >> 4) * 16));
                ldsm4(stb + XH + off, A[mi]);
            }
            #pragma unroll
            for (int njp = 0; njp < 3; njp++) {
                int nabs = wn * 48 + njp * 16 + ((lane >> 4) & 1) * 8;
                int kl_ = ks * 16 + (lane & 15);
                uint32 boff = (uint32)(kl_ * 400 + nabs * 2);
                uint32 B[4];
                ldsm4t(stb + WH + boff, B);
                #pragma unroll
                for (int mi = 0; mi < 2; mi++)
                    #pragma unroll
                    for (int j = 0; j < 2; j++)
                        mma16816h(c[mi][njp * 2 + j], A[mi], B[2*j], B[2*j+1]);
            }
        }

        if (kc < 11) {
            #pragma unroll
            for (int i = 0; i < 2; i++) {
                int f = tid + i * 512, r = f >> 3, g8 = (f & 7) * 8;
                uint4 v = make_uint4(packh2(rx[i][0].x, rx[i][0].y), packh2(rx[i][0].z, rx[i][0].w),
                                     packh2(rx[i][1].x, rx[i][1].y), packh2(rx[i][1].z, rx[i][1].w));
                *reinterpret_cast<uint4*>(nxt + XH + sw128((uint32)(r * 128 + g8 * 2))) = v;
            }
            #pragma unroll
            for (int i = 0; i < 6; i++) {
                int s_ = tid + i * 512;
                int kk = s_ / 48, q = s_ % 48;
                *reinterpret_cast<uint2*>(nxt + WH + kk * 400 + q * 8)
                    = make_uint2(packh2(rw[i].x, rw[i].y), packh2(rw[i].z, rw[i].w));
            }
        }
    }

    const int g = lane >> 2, t = lane & 3;
    uint32* gq = reinterpret_cast<uint32*>(g_q);
    uint32* gk = reinterpret_cast<uint32*>(g_k);
    uint32* gv = reinterpret_cast<uint32*>(g_v);
    #pragma unroll
    for (int mi = 0; mi < 2; mi++)
        #pragma unroll
        for (int nj = 0; nj < 6; nj++)
            #pragma unroll
            for (int h = 0; h < 2; h++) {
                size_t row = (size_t)(row0 + wm * 32 + mi * 16 + h * 8 + g);
                int colp = wn * 24 + nj * 4 + t;
                float v0 = c[mi][nj][h * 2], v1 = c[mi][nj][h * 2 + 1];
                if (colp < 32)      gq[row * 32 + colp]      = packh2(v0 * SL2E, v1 * SL2E);
                else if (colp < 64) gk[row * 32 + colp - 32] = packh2(v0, v1);
                else                gv[row * 32 + colp - 64] = packh2(v0, v1);
            }
}

// ===========================================================================
// Attention (persistent, work-queue) + fused combine. grid 296, 2 CTAs/SM.
// 32q x 32k warps, 64-key stages, fp16-acc S, fully-masked warp-tiles skipped.
// ===========================================================================
#define AQ_ 0
#define AST 16384
#define STG 16384
#define KH_ 0
#define VH_ 8192
#define AOB 0
#define ALB 49152
#define AFL (ALB + 1024)
#define AUQ (AFL + 4)
#define ATTN_SMEM (AUQ + 32)
#define NUNITS 320
#define ONESH2 0x3C003C00u
#define NINFH  0xFC00u

__device__ __forceinline__ void stage_kv_async(uint32 dstb, int b, int jt, int tid)
{
    const uint32* gk = reinterpret_cast<const uint32*>(g_k);
    const uint32* gv = reinterpret_cast<const uint32*>(g_v);
    size_t base = ((size_t)b * NT + (size_t)jt * 64) * 32;
    #pragma unroll
    for (int i = 0; i < 2; i++) {
        int f = tid + i * 256;
        int r = f >> 3, c16 = f & 7;
        uint32 off = sw128((uint32)(r * 128 + c16 * 16));
        size_t gidx = base + r * 32 + c16 * 4;
        CP_ASYNC16(dstb + KH_ + off, gk + gidx);
        CP_ASYNC16(dstb + VH_ + off, gv + gidx);
    }
}

__global__ __launch_bounds__(256, 2) void attn_kernel(float* __restrict__ out)
{
    extern __shared__ char smem[];
    const uint32 sb = smem_u32(smem);
    const int tid = threadIdx.x;
    const int wid = tid >> 5, lane = tid & 31;
    const int wm = wid & 3, wk = wid >> 2;
    const int g = lane >> 2, t = lane & 3;

    volatile int* uqslot = reinterpret_cast<volatile int*>(smem + AUQ);
    volatile int* flag   = reinterpret_cast<volatile int*>(smem + AFL);

    for (;;) {
        __syncthreads();
        if (tid == 0) *uqslot = atomicAdd(&g_next, 1);
        __syncthreads();
        const int uq = *uqslot;
        if (uq >= NUNITS) break;

        const int b = uq & 7;
        const int u = 39 - (uq >> 3);
        int qi, s, ns;
        if (u < 4)       { qi = u;                  s = 0;            ns = 1; }
        else if (u < 12) { qi = 4 + ((u - 4) >> 1); s = (u - 4) & 1;  ns = 2; }
        else if (u < 24) { qi = 8 + (u - 12) / 3;   s = (u - 12) % 3; ns = 3; }
        else             { qi = 12 + ((u - 24) >> 2); s = (u - 24) & 3; ns = 4; }
        const int cnt = qi + 1;
        const int kb = 2 * (s * cnt / ns);
        const int ke = 2 * ((s + 1) * cnt / ns);

        {
            const uint32* gq = reinterpret_cast<const uint32*>(g_q);
            size_t base = ((size_t)b * NT + (size_t)qi * 128) * 32;
            #pragma unroll
            for (int i = 0; i < 4; i++) {
                int f = tid + i * 256;
                int r = f >> 3, c16 = f & 7;
                uint32 off = sw128((uint32)(r * 128 + c16 * 16));
                CP_ASYNC16(sb + AQ_ + off, gq + base + r * 32 + c16 * 4);
            }
        }
        stage_kv_async(sb + AST, b, kb, tid);
        CP_COMMIT;

        float o[2][8][4];
        float lacc[2][4];
        #pragma unroll
        for (int mi = 0; mi < 2; mi++) {
            #pragma unroll
            for (int e = 0; e < 4; e++) lacc[mi][e] = 0.f;
            #pragma unroll
            for (int nj = 0; nj < 8; nj++)
                #pragma unroll
                for (int e = 0; e < 4; e++) o[mi][nj][e] = 0.f;
        }

        for (int jt = kb; jt < ke; jt++) {
            const int p = (jt - kb) & 1;
            const uint32 stb = sb + AST + p * STG;

            CP_WAIT0;
            __syncthreads();

            if (jt + 1 < ke) {
                stage_kv_async(sb + AST + (p ^ 1) * STG, b, jt + 1, tid);
                CP_COMMIT;
            }

            // skip warp-tiles entirely above the causal diagonal (P == 0 exactly)
            const bool boundary = (jt >= 2 * qi);
            const int kofs = jt * 64 - qi * 128;
            if (boundary && (wk * 32 + kofs > wm * 32 + 31))
                continue;   // no barriers between here and loop end

            // ---- S = Q K^T in fp16 accumulators ----
            uint32 sS16[2][4][2];
            #pragma unroll
            for (int mi = 0; mi < 2; mi++)
                #pragma unroll
                for (int nj = 0; nj < 4; nj++) {
                    sS16[mi][nj][0] = 0u; sS16[mi][nj][1] = 0u;
                }

            #pragma unroll
            for (int ks = 0; ks < 4; ks++) {
                uint32 Q[2][4];
                #pragma unroll
                for (int mi = 0; mi < 2; mi++) {
                    uint32 off = sw128((uint32)((wm * 32 + mi * 16 + (lane & 15)) * 128
                                                + ks * 32 + (lane >> 4) * 16));
                    ldsm4(sb + AQ_ + off, Q[mi]);
                }
                #pragma unroll
                for (int njp = 0; njp < 2; njp++) {
                    int row = wk * 32 + njp * 16 + (lane & 7) + ((lane >> 4) & 1) * 8;
                    uint32 off = sw128((uint32)(row * 128 + ks * 32 + ((lane >> 3) & 1) * 16));
                    uint32 K[4];
                    ldsm4(stb + KH_ + off, K);
                    #pragma unroll
                    for (int mi = 0; mi < 2; mi++)
                        #pragma unroll
                        for (int j = 0; j < 2; j++)
                            mma16816hh(sS16[mi][njp * 2 + j], Q[mi], K[2*j], K[2*j+1]);
                }
            }

            // ---- mask (boundary tiles only): set halves to -inf ----
            if (boundary) {
                #pragma unroll
                for (int mi = 0; mi < 2; mi++)
                    #pragma unroll
                    for (int nj = 0; nj < 4; nj++)
                        #pragma unroll
                        for (int rr = 0; rr < 2; rr++) {
                            int rl = wm * 32 + mi * 16 + rr * 8 + g;
                            int cl = wk * 32 + nj * 8 + 2 * t;
                            uint32 v = sS16[mi][nj][rr];
                            if (cl + kofs > rl)     v = (v & 0xFFFF0000u) | NINFH;
                            if (cl + 1 + kofs > rl) v = (v & 0x0000FFFFu) | (NINFH << 16);
                            sS16[mi][nj][rr] = v;
                        }
            }

            // ---- P = exp2(S) f16x2 (C-frag == A-frag), l += P x 1, O += P V ----
            #pragma unroll
            for (int kc = 0; kc < 2; kc++) {
                uint32 aP[2][4];
                #pragma unroll
                for (int mi = 0; mi < 2; mi++) {
                    aP[mi][0] = ex2h2(sS16[mi][2*kc][0]);
                    aP[mi][1] = ex2h2(sS16[mi][2*kc][1]);
                    aP[mi][2] = ex2h2(sS16[mi][2*kc+1][0]);
                    aP[mi][3] = ex2h2(sS16[mi][2*kc+1][1]);
                    mma16816h(lacc[mi], aP[mi], ONESH2, ONESH2);
                }
                #pragma unroll
                for (int njp = 0; njp < 4; njp++) {
                    int kr = wk * 32 + kc * 16 + (lane & 15);
                    int nn = njp * 16 + ((lane >> 4) & 1) * 8;
                    uint32 off = sw128((uint32)(kr * 128 + nn * 2));
                    uint32 V[4];
                    ldsm4t(stb + VH_ + off, V);
                    #pragma unroll
                    for (int mi = 0; mi < 2; mi++)
                        #pragma unroll
                        for (int j = 0; j < 2; j++)
                            mma16816h(o[mi][njp * 2 + j], aP[mi], V[2*j], V[2*j+1]);
                }
            }
        }

        // ---- reductions & output (lacc cols are replicated row sums) ----
        __syncthreads();
        float* Obuf = reinterpret_cast<float*>(smem + AOB);
        float* lbuf = reinterpret_cast<float*>(smem + ALB);

        if (t == 0) {
            #pragma unroll
            for (int mi = 0; mi < 2; mi++) {
                lbuf[wk * 128 + wm * 32 + mi * 16 + g]     = lacc[mi][0];
                lbuf[wk * 128 + wm * 32 + mi * 16 + 8 + g] = lacc[mi][2];
            }
        }
        if (wk == 1) {
            #pragma unroll
            for (int mi = 0; mi < 2; mi++)
                #pragma unroll
                for (int nj = 0; nj < 8; nj++) {
                    int r0 = wm * 32 + mi * 16 + g;
                    int col = nj * 8 + 2 * t;
                    *reinterpret_cast<float2*>(&Obuf[r0 * 66 + col])
                        = make_float2(o[mi][nj][0], o[mi][nj][1]);
                    *reinterpret_cast<float2*>(&Obuf[(r0 + 8) * 66 + col])
                        = make_float2(o[mi][nj][2], o[mi][nj][3]);
                }
        }
        __syncthreads();

        const size_t qbase = (size_t)b * NT + (size_t)qi * 128;

        if (ns == 1) {
            if (wk == 0) {
                #pragma unroll
                for (int mi = 0; mi < 2; mi++) {
                    int ra = wm * 32 + mi * 16 + g;
                    float inva = 1.0f / (lbuf[ra] + lbuf[128 + ra]);
                    float invb = 1.0f / (lbuf[ra + 8] + lbuf[128 + ra + 8]);
                    #pragma unroll
                    for (int nj = 0; nj < 8; nj++) {
                        int col = nj * 8 + 2 * t;
                        float2 u0 = *reinterpret_cast<float2*>(&Obuf[ra * 66 + col]);
                        float2 u1 = *reinterpret_cast<float2*>(&Obuf[(ra + 8) * 66 + col]);
                        *reinterpret_cast<float2*>(&out[(qbase + ra) * 64 + col])
                            = make_float2((o[mi][nj][0] + u0.x) * inva, (o[mi][nj][1] + u0.y) * inva);
                        *reinterpret_cast<float2*>(&out[(qbase + ra + 8) * 64 + col])
                            = make_float2((o[mi][nj][2] + u1.x) * invb, (o[mi][nj][3] + u1.y) * invb);
                    }
                }
            }
        } else {
            if (wk == 0) {
                float* op = g_opart[s];
                #pragma unroll
                for (int mi = 0; mi < 2; mi++)
                    #pragma unroll
                    for (int nj = 0; nj < 8; nj++) {
                        int r0 = wm * 32 + mi * 16 + g;
                        int col = nj * 8 + 2 * t;
                        float2 u0 = *reinterpret_cast<float2*>(&Obuf[r0 * 66 + col]);
                        float2 u1 = *reinterpret_cast<float2*>(&Obuf[(r0 + 8) * 66 + col]);
                        *reinterpret_cast<float2*>(&op[(qbase + r0) * 64 + col])
                            = make_float2(o[mi][nj][0] + u0.x, o[mi][nj][1] + u0.y);
                        *reinterpret_cast<float2*>(&op[(qbase + r0 + 8) * 64 + col])
                            = make_float2(o[mi][nj][2] + u1.x, o[mi][nj][3] + u1.y);
                    }
            }
            if (tid < 128)
                g_lpart[s][qbase + tid] = lbuf[tid] + lbuf[128 + tid];

            __threadfence();
            __syncthreads();
            if (tid == 0) {
                int ticket = atomicAdd(&g_cnt[b * 16 + qi], 1);
                *flag = (ticket == ns - 1) ? 1 : 0;
            }
            __syncthreads();
            if (*flag) {
                __threadfence();
                for (int idx = tid; idx < 2048; idx += 256) {
                    int r = idx >> 4, c4 = (idx & 15) << 2;
                    size_t rowg = qbase + r;
                    float l = 0.f;
                    float4 acc = make_float4(0.f, 0.f, 0.f, 0.f);
                    for (int s2 = 0; s2 < ns; s2++) {
                        float4 tv = *reinterpret_cast<const float4*>(&g_opart[s2][rowg * 64 + c4]);
                        acc.x += tv.x; acc.y += tv.y; acc.z += tv.z; acc.w += tv.w;
                        l += g_lpart[s2][rowg];
                    }
                    float inv = 1.0f / l;
                    acc.x *= inv; acc.y *= inv; acc.z *= inv; acc.w *= inv;
                    *reinterpret_cast<float4*>(&out[rowg * 64 + c4]) = acc;
                }
            }
        }
    }
}

// ===========================================================================
extern "C" void kernel_launch(void* const* d_in, const int* in_sizes, int n_in,
                              void* d_out, int out_size)
{
    const float* x  = (const float*)d_in[0];
    const float* Wk = (const float*)d_in[1];
    const float* Wq = (const float*)d_in[2];
    const float* Wv = (const float*)d_in[3];
    float* out = (float*)d_out;

    static bool attr_done = false;
    if (!attr_done) {
        cudaFuncSetAttribute(qkv_kernel,  cudaFuncAttributeMaxDynamicSharedMemorySize, QKV_SMEM);
        cudaFuncSetAttribute(attn_kernel, cudaFuncAttributeMaxDynamicSharedMemorySize, ATTN_SMEM);
        attr_done = true;
    }

    qkv_kernel<<<BT / 128, 512, QKV_SMEM>>>(x, Wk, Wq, Wv);
    attn_kernel<<<296, 256, ATTN_SMEM>>>(out);
}